// round 3
// baseline (speedup 1.0000x reference)
#include <cuda_runtime.h>
#include <cstdint>

#define BATCH   2048
#define RNK     32
#define H_INIT  256
#define H_DYN   512
#define D_DYN   98
#define D_INIT  96
#define NSTEP   31          // STEPS-1 RK4 steps

// Pre-transposed weights. [k][u] layout => lane-coalesced loads.
__device__ float g_WtDyn[D_DYN * H_DYN];
__device__ float g_WtInit[D_INIT * H_INIT];

__global__ void prep_kernel(const float* __restrict__ Wd1,
                            const float* __restrict__ Wi1) {
    int i = blockIdx.x * blockDim.x + threadIdx.x;
    if (i < D_DYN * H_DYN) {
        int k = i / H_DYN, u = i % H_DYN;
        g_WtDyn[i] = Wd1[u * D_DYN + k];
    }
    int j = i - D_DYN * H_DYN;
    if (j >= 0 && j < D_INIT * H_INIT) {
        int k = j / H_INIT, u = j % H_INIT;
        g_WtInit[j] = Wi1[u * D_INIT + k];
    }
}

__device__ __forceinline__ float tanhf_fast(float a) {
    float r; asm("tanh.approx.f32 %0, %1;" : "=f"(r) : "f"(a)); return r;
}

// 2 warps/block, 2 samples/warp (16-lane groups), 32 dyn units per lane.
__global__ void __launch_bounds__(64) node_kernel(
    const int*   __restrict__ b_i_raw,   // int32 or int64 (sniffed)
    const float* __restrict__ b_t_n,
    const float* __restrict__ U0,
    const float* __restrict__ U1,
    const float* __restrict__ U2,
    const float* __restrict__ bi1,
    const float* __restrict__ Wi2,
    const float* __restrict__ bi2,
    const float* __restrict__ bd1,
    const float* __restrict__ Wd2,
    const float* __restrict__ bd2,
    float* __restrict__ out)
{
    __shared__ float uv[4][96];          // 4 samples per block
    const int lane = threadIdx.x & 31;
    const int g    = lane >> 4;          // sample group within warp
    const int gl   = lane & 15;          // lane within group
    const int wid  = blockIdx.x * 2 + (threadIdx.x >> 5);
    const int s    = wid * 2 + g;        // global sample id
    const int slot = (threadIdx.x >> 5) * 2 + g;
    const int ub   = gl * 4;             // float4 base within a 64-unit chunk

    // --- index dtype sniff: int64 rows have zero high words ---
    bool is64 = ((b_i_raw[1] | b_i_raw[3] | b_i_raw[5]) == 0);
    int i0, i1, i2;
    if (is64) {
        i0 = b_i_raw[(s * 3 + 0) * 2];
        i1 = b_i_raw[(s * 3 + 1) * 2];
        i2 = b_i_raw[(s * 3 + 2) * 2];
    } else {
        i0 = b_i_raw[s * 3 + 0];
        i1 = b_i_raw[s * 3 + 1];
        i2 = b_i_raw[s * 3 + 2];
    }

    // --- gather Uvec (96) into shared; 16 lanes x 2 elems per matrix ---
    #pragma unroll
    for (int j = gl; j < 32; j += 16) {
        uv[slot][j]      = U0[(size_t)i0 * RNK + j];
        uv[slot][32 + j] = U1[(size_t)i1 * RNK + j];
        uv[slot][64 + j] = U2[(size_t)i2 * RNK + j];
    }
    __syncwarp();
    const float* uvs = uv[slot];

    // ======================= dyn-net precompute =======================
    // c[u] = bd1[u] + Wd1[u,2:]·Uvec      (per-sample constant, 32 units/lane)
    float c[32];
    #pragma unroll
    for (int q = 0; q < 8; q++) {
        float4 bv = *(const float4*)(bd1 + q * 64 + ub);
        c[q*4+0] = bv.x; c[q*4+1] = bv.y;
        c[q*4+2] = bv.z; c[q*4+3] = bv.w;
    }
    #pragma unroll 2
    for (int k = 0; k < 96; k++) {
        float uk = uvs[k];
        const float* row = g_WtDyn + (k + 2) * H_DYN + ub;
        #pragma unroll
        for (int q = 0; q < 8; q++) {
            float4 wv = *(const float4*)(row + q * 64);
            c[q*4+0] = fmaf(wv.x, uk, c[q*4+0]);
            c[q*4+1] = fmaf(wv.y, uk, c[q*4+1]);
            c[q*4+2] = fmaf(wv.z, uk, c[q*4+2]);
            c[q*4+3] = fmaf(wv.w, uk, c[q*4+3]);
        }
    }

    // ======================= init net: x0 (16 units/lane) ==============
    float ai[16];
    #pragma unroll
    for (int q = 0; q < 4; q++) {
        float4 bv = *(const float4*)(bi1 + q * 64 + ub);
        ai[q*4+0] = bv.x; ai[q*4+1] = bv.y;
        ai[q*4+2] = bv.z; ai[q*4+3] = bv.w;
    }
    #pragma unroll 2
    for (int k = 0; k < 96; k++) {
        float uk = uvs[k];
        const float* row = g_WtInit + k * H_INIT + ub;
        #pragma unroll
        for (int q = 0; q < 4; q++) {
            float4 wv = *(const float4*)(row + q * 64);
            ai[q*4+0] = fmaf(wv.x, uk, ai[q*4+0]);
            ai[q*4+1] = fmaf(wv.y, uk, ai[q*4+1]);
            ai[q*4+2] = fmaf(wv.z, uk, ai[q*4+2]);
            ai[q*4+3] = fmaf(wv.w, uk, ai[q*4+3]);
        }
    }
    float p0 = 0.f;
    #pragma unroll
    for (int q = 0; q < 4; q++) {
        float4 wv = *(const float4*)(Wi2 + q * 64 + ub);
        p0 = fmaf(tanhf_fast(ai[q*4+0]), wv.x, p0);
        p0 = fmaf(tanhf_fast(ai[q*4+1]), wv.y, p0);
        p0 = fmaf(tanhf_fast(ai[q*4+2]), wv.z, p0);
        p0 = fmaf(tanhf_fast(ai[q*4+3]), wv.w, p0);
    }
    #pragma unroll
    for (int off = 8; off > 0; off >>= 1)
        p0 += __shfl_xor_sync(0xffffffffu, p0, off);

    float x = p0 + bi2[0];
    const float bd2v = bd2[0];

    // ======================= dyn per-eval weights =======================
    const float scaleT = b_t_n[s];
    float w0l[32], w1l[32], w2l[32];
    #pragma unroll
    for (int q = 0; q < 8; q++) {
        float4 a0 = *(const float4*)(g_WtDyn + 0 * H_DYN + q * 64 + ub);
        float4 a1 = *(const float4*)(g_WtDyn + 1 * H_DYN + q * 64 + ub);
        float4 a2 = *(const float4*)(Wd2 + q * 64 + ub);
        w0l[q*4+0] = a0.x * scaleT; w0l[q*4+1] = a0.y * scaleT;
        w0l[q*4+2] = a0.z * scaleT; w0l[q*4+3] = a0.w * scaleT;
        w1l[q*4+0] = a1.x; w1l[q*4+1] = a1.y;
        w1l[q*4+2] = a1.z; w1l[q*4+3] = a1.w;
        w2l[q*4+0] = a2.x; w2l[q*4+1] = a2.y;
        w2l[q*4+2] = a2.z; w2l[q*4+3] = a2.w;
    }

    // ======================= RK4 loop =======================
    // dyn(t,x) = (sum_u tanh(c_u + w0l_u*t + w1l_u*x) * w2_u + bd2) * scaleT
    auto feval = [&](float t, float xv) -> float {
        float acc0 = 0.f, acc1 = 0.f, acc2 = 0.f, acc3 = 0.f;
        #pragma unroll
        for (int i = 0; i < 32; i += 4) {
            float a0 = fmaf(w0l[i],     t, fmaf(w1l[i],     xv, c[i]));
            float a1 = fmaf(w0l[i + 1], t, fmaf(w1l[i + 1], xv, c[i + 1]));
            float a2 = fmaf(w0l[i + 2], t, fmaf(w1l[i + 2], xv, c[i + 2]));
            float a3 = fmaf(w0l[i + 3], t, fmaf(w1l[i + 3], xv, c[i + 3]));
            acc0 = fmaf(tanhf_fast(a0), w2l[i],     acc0);
            acc1 = fmaf(tanhf_fast(a1), w2l[i + 1], acc1);
            acc2 = fmaf(tanhf_fast(a2), w2l[i + 2], acc2);
            acc3 = fmaf(tanhf_fast(a3), w2l[i + 3], acc3);
        }
        float p = (acc0 + acc1) + (acc2 + acc3);
        #pragma unroll
        for (int off = 8; off > 0; off >>= 1)
            p += __shfl_xor_sync(0xffffffffu, p, off);
        return (p + bd2v) * scaleT;
    };

    const float hh = 1.f / 31.f;
    #pragma unroll 1
    for (int stp = 0; stp < NSTEP; stp++) {
        float t0 = (float)stp * hh;
        float k1 = feval(t0,             x);
        float k2 = feval(t0 + 0.5f * hh, fmaf(0.5f * hh, k1, x));
        float k3 = feval(t0 + 0.5f * hh, fmaf(0.5f * hh, k2, x));
        float k4 = feval(t0 + hh,        fmaf(hh, k3, x));
        x += (hh / 6.f) * (k1 + 2.f * (k2 + k3) + k4);
    }

    if (gl == 0) out[s] = x;
}

extern "C" void kernel_launch(void* const* d_in, const int* in_sizes, int n_in,
                              void* d_out, int out_size) {
    const int*   b_i  = (const int*)  d_in[0];
    const float* b_t  = (const float*)d_in[1];
    const float* U0   = (const float*)d_in[2];
    const float* U1   = (const float*)d_in[3];
    const float* U2   = (const float*)d_in[4];
    const float* Wi1  = (const float*)d_in[5];
    const float* bi1  = (const float*)d_in[6];
    const float* Wi2  = (const float*)d_in[7];
    const float* bi2  = (const float*)d_in[8];
    const float* Wd1  = (const float*)d_in[9];
    const float* bd1  = (const float*)d_in[10];
    const float* Wd2  = (const float*)d_in[11];
    const float* bd2  = (const float*)d_in[12];

    int tot = D_DYN * H_DYN + D_INIT * H_INIT;
    prep_kernel<<<(tot + 255) / 256, 256>>>(Wd1, Wi1);
    // 512 blocks x 64 threads: 2 warps/block, 2 samples/warp -> 2048 samples
    node_kernel<<<BATCH / 4, 64>>>(b_i, b_t, U0, U1, U2,
                                   bi1, Wi2, bi2, bd1, Wd2, bd2,
                                   (float*)d_out);
}

// round 4
// speedup vs baseline: 1.0259x; 1.0259x over previous
#include <cuda_runtime.h>
#include <cstdint>

#define BATCH   2048
#define RNK     32
#define H_INIT  256
#define H_DYN   512
#define D_DYN   98
#define D_INIT  96
#define NSTEP   31          // STEPS-1 RK4 steps

// Pre-transposed weights. [k][u] layout => lane-coalesced loads.
__device__ float g_WtDyn[D_DYN * H_DYN];
__device__ float g_WtInit[D_INIT * H_INIT];

__global__ void prep_kernel(const float* __restrict__ Wd1,
                            const float* __restrict__ Wi1) {
    int i = blockIdx.x * blockDim.x + threadIdx.x;
    if (i < D_DYN * H_DYN) {
        int k = i / H_DYN, u = i % H_DYN;
        g_WtDyn[i] = Wd1[u * D_DYN + k];
    }
    int j = i - D_DYN * H_DYN;
    if (j >= 0 && j < D_INIT * H_INIT) {
        int k = j / H_INIT, u = j % H_INIT;
        g_WtInit[j] = Wi1[u * D_INIT + k];
    }
}

__device__ __forceinline__ float tanhf_fast(float a) {
    float r; asm("tanh.approx.f32 %0, %1;" : "=f"(r) : "f"(a)); return r;
}

// 2 warps/block; each warp owns TWO samples as independent full-width
// dataflows (16 units/lane each) so their MUFU bursts and SHFL trees
// interleave in one instruction stream.
__global__ void __launch_bounds__(64) node_kernel(
    const int*   __restrict__ b_i_raw,   // int32 or int64 (sniffed)
    const float* __restrict__ b_t_n,
    const float* __restrict__ U0,
    const float* __restrict__ U1,
    const float* __restrict__ U2,
    const float* __restrict__ bi1,
    const float* __restrict__ Wi2,
    const float* __restrict__ bi2,
    const float* __restrict__ bd1,
    const float* __restrict__ Wd2,
    const float* __restrict__ bd2,
    float* __restrict__ out)
{
    __shared__ float uv[4][96];          // 2 warps x 2 samples
    const int lane = threadIdx.x & 31;
    const int wib  = threadIdx.x >> 5;   // warp in block
    const int wid  = blockIdx.x * 2 + wib;
    const int sA   = wid * 2;
    const int sB   = sA + 1;
    const int ub   = lane * 4;

    // --- index dtype sniff: int64 rows have zero high words ---
    bool is64 = ((b_i_raw[1] | b_i_raw[3] | b_i_raw[5]) == 0);
    int iA0, iA1, iA2, iB0, iB1, iB2;
    if (is64) {
        iA0 = b_i_raw[(sA * 3 + 0) * 2];
        iA1 = b_i_raw[(sA * 3 + 1) * 2];
        iA2 = b_i_raw[(sA * 3 + 2) * 2];
        iB0 = b_i_raw[(sB * 3 + 0) * 2];
        iB1 = b_i_raw[(sB * 3 + 1) * 2];
        iB2 = b_i_raw[(sB * 3 + 2) * 2];
    } else {
        iA0 = b_i_raw[sA * 3 + 0];
        iA1 = b_i_raw[sA * 3 + 1];
        iA2 = b_i_raw[sA * 3 + 2];
        iB0 = b_i_raw[sB * 3 + 0];
        iB1 = b_i_raw[sB * 3 + 1];
        iB2 = b_i_raw[sB * 3 + 2];
    }

    // --- gather Uvec (96) into shared for both samples ---
    float* uvA = uv[wib * 2 + 0];
    float* uvB = uv[wib * 2 + 1];
    uvA[lane]      = U0[(size_t)iA0 * RNK + lane];
    uvA[32 + lane] = U1[(size_t)iA1 * RNK + lane];
    uvA[64 + lane] = U2[(size_t)iA2 * RNK + lane];
    uvB[lane]      = U0[(size_t)iB0 * RNK + lane];
    uvB[32 + lane] = U1[(size_t)iB1 * RNK + lane];
    uvB[64 + lane] = U2[(size_t)iB2 * RNK + lane];
    __syncwarp();

    // ======================= dyn-net precompute =======================
    // c[u] = bd1[u] + Wd1[u,2:]·Uvec   for both samples; weights shared.
    float cA[16], cB[16];
    #pragma unroll
    for (int q = 0; q < 4; q++) {
        float4 bv = *(const float4*)(bd1 + q * 128 + ub);
        cA[q*4+0] = bv.x; cA[q*4+1] = bv.y; cA[q*4+2] = bv.z; cA[q*4+3] = bv.w;
        cB[q*4+0] = bv.x; cB[q*4+1] = bv.y; cB[q*4+2] = bv.z; cB[q*4+3] = bv.w;
    }
    #pragma unroll 2
    for (int k = 0; k < 96; k++) {
        float ukA = uvA[k];
        float ukB = uvB[k];
        const float* row = g_WtDyn + (k + 2) * H_DYN + ub;
        #pragma unroll
        for (int q = 0; q < 4; q++) {
            float4 wv = *(const float4*)(row + q * 128);
            cA[q*4+0] = fmaf(wv.x, ukA, cA[q*4+0]);
            cA[q*4+1] = fmaf(wv.y, ukA, cA[q*4+1]);
            cA[q*4+2] = fmaf(wv.z, ukA, cA[q*4+2]);
            cA[q*4+3] = fmaf(wv.w, ukA, cA[q*4+3]);
            cB[q*4+0] = fmaf(wv.x, ukB, cB[q*4+0]);
            cB[q*4+1] = fmaf(wv.y, ukB, cB[q*4+1]);
            cB[q*4+2] = fmaf(wv.z, ukB, cB[q*4+2]);
            cB[q*4+3] = fmaf(wv.w, ukB, cB[q*4+3]);
        }
    }

    // ======================= init net: x0 for both =======================
    float aiA[8], aiB[8];
    #pragma unroll
    for (int q = 0; q < 2; q++) {
        float4 bv = *(const float4*)(bi1 + q * 128 + ub);
        aiA[q*4+0] = bv.x; aiA[q*4+1] = bv.y; aiA[q*4+2] = bv.z; aiA[q*4+3] = bv.w;
        aiB[q*4+0] = bv.x; aiB[q*4+1] = bv.y; aiB[q*4+2] = bv.z; aiB[q*4+3] = bv.w;
    }
    #pragma unroll 2
    for (int k = 0; k < 96; k++) {
        float ukA = uvA[k];
        float ukB = uvB[k];
        const float* row = g_WtInit + k * H_INIT + ub;
        #pragma unroll
        for (int q = 0; q < 2; q++) {
            float4 wv = *(const float4*)(row + q * 128);
            aiA[q*4+0] = fmaf(wv.x, ukA, aiA[q*4+0]);
            aiA[q*4+1] = fmaf(wv.y, ukA, aiA[q*4+1]);
            aiA[q*4+2] = fmaf(wv.z, ukA, aiA[q*4+2]);
            aiA[q*4+3] = fmaf(wv.w, ukA, aiA[q*4+3]);
            aiB[q*4+0] = fmaf(wv.x, ukB, aiB[q*4+0]);
            aiB[q*4+1] = fmaf(wv.y, ukB, aiB[q*4+1]);
            aiB[q*4+2] = fmaf(wv.z, ukB, aiB[q*4+2]);
            aiB[q*4+3] = fmaf(wv.w, ukB, aiB[q*4+3]);
        }
    }
    float pA = 0.f, pB = 0.f;
    #pragma unroll
    for (int q = 0; q < 2; q++) {
        float4 wv = *(const float4*)(Wi2 + q * 128 + ub);
        pA = fmaf(tanhf_fast(aiA[q*4+0]), wv.x, pA);
        pB = fmaf(tanhf_fast(aiB[q*4+0]), wv.x, pB);
        pA = fmaf(tanhf_fast(aiA[q*4+1]), wv.y, pA);
        pB = fmaf(tanhf_fast(aiB[q*4+1]), wv.y, pB);
        pA = fmaf(tanhf_fast(aiA[q*4+2]), wv.z, pA);
        pB = fmaf(tanhf_fast(aiB[q*4+2]), wv.z, pB);
        pA = fmaf(tanhf_fast(aiA[q*4+3]), wv.w, pA);
        pB = fmaf(tanhf_fast(aiB[q*4+3]), wv.w, pB);
    }
    #pragma unroll
    for (int off = 16; off > 0; off >>= 1) {
        pA += __shfl_xor_sync(0xffffffffu, pA, off);
        pB += __shfl_xor_sync(0xffffffffu, pB, off);
    }

    float xA = pA + bi2[0];
    float xB = pB + bi2[0];
    const float bd2v = bd2[0];
    const float sTA = b_t_n[sA];
    const float sTB = b_t_n[sB];

    // ======================= shared dyn weights =======================
    float w0l[16], w1l[16], w2l[16];
    #pragma unroll
    for (int q = 0; q < 4; q++) {
        float4 a0 = *(const float4*)(g_WtDyn + 0 * H_DYN + q * 128 + ub);
        float4 a1 = *(const float4*)(g_WtDyn + 1 * H_DYN + q * 128 + ub);
        float4 a2 = *(const float4*)(Wd2 + q * 128 + ub);
        w0l[q*4+0] = a0.x; w0l[q*4+1] = a0.y; w0l[q*4+2] = a0.z; w0l[q*4+3] = a0.w;
        w1l[q*4+0] = a1.x; w1l[q*4+1] = a1.y; w1l[q*4+2] = a1.z; w1l[q*4+3] = a1.w;
        w2l[q*4+0] = a2.x; w2l[q*4+1] = a2.y; w2l[q*4+2] = a2.z; w2l[q*4+3] = a2.w;
    }

    // ======================= RK4 loop (dual sample) =======================
    // dyn(t,x) = (sum_u tanh(c_u + w0_u*(t*sT) + w1_u*x) * w2_u + bd2) * sT
    float kAo, kBo;
    auto feval2 = [&](float t, float xvA, float xvB) {
        float tsA = t * sTA;
        float tsB = t * sTB;
        float accA0 = 0.f, accA1 = 0.f, accB0 = 0.f, accB1 = 0.f;
        #pragma unroll
        for (int i = 0; i < 16; i += 2) {
            float aA0 = fmaf(w0l[i],   tsA, fmaf(w1l[i],   xvA, cA[i]));
            float aB0 = fmaf(w0l[i],   tsB, fmaf(w1l[i],   xvB, cB[i]));
            float aA1 = fmaf(w0l[i+1], tsA, fmaf(w1l[i+1], xvA, cA[i+1]));
            float aB1 = fmaf(w0l[i+1], tsB, fmaf(w1l[i+1], xvB, cB[i+1]));
            accA0 = fmaf(tanhf_fast(aA0), w2l[i],   accA0);
            accB0 = fmaf(tanhf_fast(aB0), w2l[i],   accB0);
            accA1 = fmaf(tanhf_fast(aA1), w2l[i+1], accA1);
            accB1 = fmaf(tanhf_fast(aB1), w2l[i+1], accB1);
        }
        float rA = accA0 + accA1;
        float rB = accB0 + accB1;
        #pragma unroll
        for (int off = 16; off > 0; off >>= 1) {
            rA += __shfl_xor_sync(0xffffffffu, rA, off);
            rB += __shfl_xor_sync(0xffffffffu, rB, off);
        }
        kAo = (rA + bd2v) * sTA;
        kBo = (rB + bd2v) * sTB;
    };

    const float hh = 1.f / 31.f;
    #pragma unroll 1
    for (int stp = 0; stp < NSTEP; stp++) {
        float t0 = (float)stp * hh;
        feval2(t0, xA, xB);
        float kA1 = kAo, kB1 = kBo;
        feval2(t0 + 0.5f * hh, fmaf(0.5f * hh, kA1, xA), fmaf(0.5f * hh, kB1, xB));
        float kA2 = kAo, kB2 = kBo;
        feval2(t0 + 0.5f * hh, fmaf(0.5f * hh, kA2, xA), fmaf(0.5f * hh, kB2, xB));
        float kA3 = kAo, kB3 = kBo;
        feval2(t0 + hh, fmaf(hh, kA3, xA), fmaf(hh, kB3, xB));
        xA += (hh / 6.f) * (kA1 + 2.f * (kA2 + kA3) + kAo);
        xB += (hh / 6.f) * (kB1 + 2.f * (kB2 + kB3) + kBo);
    }

    if (lane == 0) {
        out[sA] = xA;
        out[sB] = xB;
    }
}

extern "C" void kernel_launch(void* const* d_in, const int* in_sizes, int n_in,
                              void* d_out, int out_size) {
    const int*   b_i  = (const int*)  d_in[0];
    const float* b_t  = (const float*)d_in[1];
    const float* U0   = (const float*)d_in[2];
    const float* U1   = (const float*)d_in[3];
    const float* U2   = (const float*)d_in[4];
    const float* Wi1  = (const float*)d_in[5];
    const float* bi1  = (const float*)d_in[6];
    const float* Wi2  = (const float*)d_in[7];
    const float* bi2  = (const float*)d_in[8];
    const float* Wd1  = (const float*)d_in[9];
    const float* bd1  = (const float*)d_in[10];
    const float* Wd2  = (const float*)d_in[11];
    const float* bd2  = (const float*)d_in[12];

    int tot = D_DYN * H_DYN + D_INIT * H_INIT;
    prep_kernel<<<(tot + 255) / 256, 256>>>(Wd1, Wi1);
    // 512 blocks x 64 threads: 2 warps/block, 2 samples/warp -> 2048 samples
    node_kernel<<<BATCH / 4, 64>>>(b_i, b_t, U0, U1, U2,
                                   bi1, Wi2, bi2, bd1, Wd2, bd2,
                                   (float*)d_out);
}